// round 16
// baseline (speedup 1.0000x reference)
#include <cuda_runtime.h>
#include <cuda_fp16.h>
#include <cstdint>

#define N_NODES 8192
#define N_EDGES 262144
#define D 512
#define MW 256   // 8192 bits / 32 = 256 mask words per row

// Scratch (device globals; no allocations allowed)
__device__ unsigned int g_mask[N_NODES * MW];           // 8 MB adjacency bitmask
__device__ float        g_dinv[N_NODES];                // D^{-1/2}
__device__ __align__(16) __half g_h[N_NODES * D];       // H = X@W (UNscaled), fp16
__device__ int          g_is64;                         // edge_index dtype flag
__device__ __align__(16) __half g_xh[N_NODES * D];      // fp16 X
__device__ __align__(16) __half g_wh[D * D];            // fp16 W

// ---------------------------------------------------------------------------
// 0) detect edge_index dtype (int64 vs int32): sample 512 odd int32 words.
// ---------------------------------------------------------------------------
__global__ void k_detect(const int* __restrict__ ei32) {
    int t = threadIdx.x;                   // 0..127
    const int4* p = (const int4*)ei32;
    int4 a = p[2 * t];
    int4 b = p[2 * t + 1];
    int nz = a.y | a.w | b.y | b.w;
    int any = __syncthreads_or(nz != 0);
    if (t == 0) g_is64 = any ? 0 : 1;
}

// ---------------------------------------------------------------------------
// 1) zero bitmask
// ---------------------------------------------------------------------------
__global__ void k_zero_mask() {
    int i = blockIdx.x * blockDim.x + threadIdx.x;   // 512 blocks x 256 thr
    uint4* p = (uint4*)g_mask;
    uint4 z = make_uint4(0, 0, 0, 0);
    #pragma unroll
    for (int k = 0; k < 4; k++)
        p[i + k * 131072] = z;
}

// ---------------------------------------------------------------------------
// 2) symmetric edge scatter, 2 edges per thread
// ---------------------------------------------------------------------------
__global__ void k_scatter(const void* __restrict__ ei_raw) {
    int e2 = blockIdx.x * blockDim.x + threadIdx.x;
    if (e2 >= N_EDGES / 2) return;
    int u0, u1, v0, v1;
    if (g_is64) {
        const longlong2* pe = (const longlong2*)ei_raw;
        longlong2 uu = pe[e2];
        longlong2 vv = pe[N_EDGES / 2 + e2];
        u0 = (int)uu.x; u1 = (int)uu.y;
        v0 = (int)vv.x; v1 = (int)vv.y;
    } else {
        const int2* pe = (const int2*)ei_raw;
        int2 uu = pe[e2];
        int2 vv = pe[N_EDGES / 2 + e2];
        u0 = uu.x; u1 = uu.y;
        v0 = vv.x; v1 = vv.y;
    }
    u0 &= (N_NODES - 1); u1 &= (N_NODES - 1);
    v0 &= (N_NODES - 1); v1 &= (N_NODES - 1);
    atomicOr(&g_mask[u0 * MW + (v0 >> 5)], 1u << (v0 & 31));
    atomicOr(&g_mask[v0 * MW + (u0 >> 5)], 1u << (u0 & 31));
    atomicOr(&g_mask[u1 * MW + (v1 >> 5)], 1u << (v1 & 31));
    atomicOr(&g_mask[v1 * MW + (u1 >> 5)], 1u << (u1 & 31));
}

// ---------------------------------------------------------------------------
// 3) degree + dinv
// ---------------------------------------------------------------------------
__global__ void k_degree() {
    int row  = blockIdx.x * (blockDim.x >> 5) + (threadIdx.x >> 5);
    int lane = threadIdx.x & 31;
    if (row >= N_NODES) return;
    const uint4* m = (const uint4*)&g_mask[row * MW];
    int cnt = 0;
    #pragma unroll
    for (int w = 0; w < 2; w++) {
        uint4 q = m[lane + w * 32];
        cnt += __popc(q.x) + __popc(q.y) + __popc(q.z) + __popc(q.w);
    }
    #pragma unroll
    for (int o = 16; o; o >>= 1) cnt += __shfl_xor_sync(0xffffffffu, cnt, o);
    if (lane == 0) g_dinv[row] = rsqrtf((float)(cnt + 1));
}

// ---------------------------------------------------------------------------
// 3b) fused fp32 -> fp16 convert: 16 floats per thread
// ---------------------------------------------------------------------------
#define XBLOCKS 1024
#define WBLOCKS 64

__global__ void k_cvt_xw(const float4* __restrict__ x, uint4* __restrict__ xh,
                         const float4* __restrict__ w, uint4* __restrict__ wh) {
    int b = blockIdx.x;
    const float4* src;
    uint4* dst;
    int i;
    if (b < XBLOCKS) {
        src = x; dst = xh;
        i = b * blockDim.x + threadIdx.x;
    } else {
        src = w; dst = wh;
        i = (b - XBLOCKS) * blockDim.x + threadIdx.x;
    }
    float4 a0 = src[4 * i];
    float4 a1 = src[4 * i + 1];
    float4 a2 = src[4 * i + 2];
    float4 a3 = src[4 * i + 3];
    uint4 o0, o1;
    __half2 h;
    h = __floats2half2_rn(a0.x, a0.y); o0.x = *(uint32_t*)&h;
    h = __floats2half2_rn(a0.z, a0.w); o0.y = *(uint32_t*)&h;
    h = __floats2half2_rn(a1.x, a1.y); o0.z = *(uint32_t*)&h;
    h = __floats2half2_rn(a1.z, a1.w); o0.w = *(uint32_t*)&h;
    h = __floats2half2_rn(a2.x, a2.y); o1.x = *(uint32_t*)&h;
    h = __floats2half2_rn(a2.z, a2.w); o1.y = *(uint32_t*)&h;
    h = __floats2half2_rn(a3.x, a3.y); o1.z = *(uint32_t*)&h;
    h = __floats2half2_rn(a3.z, a3.w); o1.w = *(uint32_t*)&h;
    dst[2 * i]     = o0;
    dst[2 * i + 1] = o1;
}

// ---------------------------------------------------------------------------
// 4) Tensor-core GEMM (mma.sync fp16, fp32 acc), 4-stage cp.async pipeline,
//    128x128 CTA tile, 4 warps, 64x64 warp tile, grid (4,64).
//    NEW: fragment double-buffering — both k-chunks' ldsm batches are issued
//    before the first mma block so the second batch overlaps the 32-deep
//    independent HMMA stream (volatile asm blocks ptxas from doing this).
// ---------------------------------------------------------------------------
#define GBM 128
#define GBN 128
#define GBK 32
#define ASTRIDE 40    // halves: 32 + 8 pad
#define BSTRIDE 144   // halves: 128 + 16 pad
#define NSTAGE 4
#define A_BYTES (GBM * ASTRIDE * 2)          // 10240
#define B_BYTES (GBK * BSTRIDE * 2)          // 9216
#define STAGE_BYTES (A_BYTES + B_BYTES)      // 19456
#define SMEM_GEMM (NSTAGE * STAGE_BYTES)     // 77824
#define KTILES (D / GBK)                     // 16

__device__ __forceinline__ uint32_t smem_u32(const void* p) {
    uint32_t a;
    asm("{ .reg .u64 t; cvta.to.shared.u64 t, %1; cvt.u32.u64 %0, t; }" : "=r"(a) : "l"(p));
    return a;
}
__device__ __forceinline__ void cp16(uint32_t dst, const void* src) {
    asm volatile("cp.async.cg.shared.global [%0], [%1], 16;" :: "r"(dst), "l"(src) : "memory");
}
__device__ __forceinline__ void ldsm_x4(uint32_t* r, const void* p) {
    uint32_t a = (uint32_t)__cvta_generic_to_shared(p);
    asm volatile("ldmatrix.sync.aligned.m8n8.x4.shared.b16 {%0,%1,%2,%3}, [%4];"
                 : "=r"(r[0]), "=r"(r[1]), "=r"(r[2]), "=r"(r[3]) : "r"(a));
}
__device__ __forceinline__ void ldsm_x4t(uint32_t* r, const void* p) {
    uint32_t a = (uint32_t)__cvta_generic_to_shared(p);
    asm volatile("ldmatrix.sync.aligned.m8n8.x4.trans.shared.b16 {%0,%1,%2,%3}, [%4];"
                 : "=r"(r[0]), "=r"(r[1]), "=r"(r[2]), "=r"(r[3]) : "r"(a));
}
__device__ __forceinline__ void mma16816(float* c, const uint32_t* a, const uint32_t* b) {
    asm volatile("mma.sync.aligned.m16n8k16.row.col.f32.f16.f16.f32 "
                 "{%0,%1,%2,%3}, {%4,%5,%6,%7}, {%8,%9}, {%0,%1,%2,%3};"
                 : "+f"(c[0]), "+f"(c[1]), "+f"(c[2]), "+f"(c[3])
                 : "r"(a[0]), "r"(a[1]), "r"(a[2]), "r"(a[3]), "r"(b[0]), "r"(b[1]));
}

__global__ __launch_bounds__(128) void k_gemm_mma() {
    extern __shared__ char dsm[];
    uint32_t sb = smem_u32(dsm);

    int tid  = threadIdx.x;            // 0..127
    int lane = tid & 31;
    int wid  = tid >> 5;               // 0..3
    int wm   = wid & 1;                // rows wm*64
    int wn   = wid >> 1;               // cols wn*64
    int rowBase = blockIdx.y * GBM;
    int colBase = blockIdx.x * GBN;

    float acc[4][8][4];
    #pragma unroll
    for (int mi = 0; mi < 4; mi++)
        #pragma unroll
        for (int ni = 0; ni < 8; ni++)
            #pragma unroll
            for (int q = 0; q < 4; q++) acc[mi][ni][q] = 0.0f;

    auto issue = [&](int t) {
        uint32_t base = sb + (t % NSTAGE) * STAGE_BYTES;
        #pragma unroll
        for (int k = 0; k < 4; k++) {              // A: 128x32 halves, 512 chunks
            int i = tid + k * 128;
            int r = i >> 2, cc = i & 3;
            cp16(base + r * 80 + cc * 16,
                 &g_xh[(rowBase + r) * D + t * GBK + cc * 8]);
        }
        #pragma unroll
        for (int k = 0; k < 4; k++) {              // B: 32x128 halves, 512 chunks
            int i = tid + k * 128;
            int r = i >> 4, cc = i & 15;
            cp16(base + A_BYTES + r * 288 + cc * 16,
                 &g_wh[(t * GBK + r) * D + colBase + cc * 8]);
        }
        asm volatile("cp.async.commit_group;" ::: "memory");
    };

    // fragment loader for one 16-wide k-chunk
    auto ldfrags = [&](const __half* Ah, const __half* Bh, int kk,
                       uint32_t af[4][4], uint32_t bf[8][2]) {
        #pragma unroll
        for (int mi = 0; mi < 4; mi++) {
            int r = wm * 64 + mi * 16 + (lane & 15);
            int c = kk + ((lane >> 4) << 3);
            ldsm_x4(af[mi], &Ah[r * ASTRIDE + c]);
        }
        #pragma unroll
        for (int np = 0; np < 4; np++) {
            int r = kk + (lane & 15);
            int c = wn * 64 + np * 16 + ((lane >> 4) << 3);
            uint32_t t4[4];
            ldsm_x4t(t4, &Bh[r * BSTRIDE + c]);
            bf[2 * np][0] = t4[0]; bf[2 * np][1] = t4[1];
            bf[2 * np + 1][0] = t4[2]; bf[2 * np + 1][1] = t4[3];
        }
    };

    #pragma unroll
    for (int t = 0; t < NSTAGE - 1; t++) issue(t);

    for (int kt = 0; kt < KTILES; kt++) {
        __syncthreads();
        if (kt + NSTAGE - 1 < KTILES) issue(kt + NSTAGE - 1);
        else asm volatile("cp.async.commit_group;" ::: "memory");
        asm volatile("cp.async.wait_group %0;" :: "n"(NSTAGE - 1) : "memory");
        __syncthreads();

        const __half* Ah = (const __half*)(dsm + (kt % NSTAGE) * STAGE_BYTES);
        const __half* Bh = (const __half*)(dsm + (kt % NSTAGE) * STAGE_BYTES + A_BYTES);

        // double-buffered fragments: issue BOTH chunk loads before first mma
        uint32_t afA[4][4], bfA[8][2];
        uint32_t afB[4][4], bfB[8][2];
        ldfrags(Ah, Bh, 0,  afA, bfA);
        ldfrags(Ah, Bh, 16, afB, bfB);   // overlaps the mma block below

        #pragma unroll
        for (int mi = 0; mi < 4; mi++)
            #pragma unroll
            for (int ni = 0; ni < 8; ni++)
                mma16816(acc[mi][ni], afA[mi], bfA[ni]);
        #pragma unroll
        for (int mi = 0; mi < 4; mi++)
            #pragma unroll
            for (int ni = 0; ni < 8; ni++)
                mma16816(acc[mi][ni], afB[mi], bfB[ni]);
    }

    // epilogue: write fp16 H (no scaling)
    int g  = lane >> 2;
    int tg = lane & 3;
    #pragma unroll
    for (int mi = 0; mi < 4; mi++) {
        int row0 = rowBase + wm * 64 + mi * 16 + g;
        int row1 = row0 + 8;
        #pragma unroll
        for (int ni = 0; ni < 8; ni++) {
            int col = colBase + wn * 64 + ni * 8 + tg * 2;
            __half2 v0 = __floats2half2_rn(acc[mi][ni][0], acc[mi][ni][1]);
            __half2 v1 = __floats2half2_rn(acc[mi][ni][2], acc[mi][ni][3]);
            *(__half2*)&g_h[row0 * D + col] = v0;
            *(__half2*)&g_h[row1 * D + col] = v1;
        }
    }
}

// ---------------------------------------------------------------------------
// 5) SpMM gather (fp16 payload, 16B loads, per-neighbor dinv scaling)
// ---------------------------------------------------------------------------
#define LIST_CAP 4096

__device__ __forceinline__ void fma_h8(float4& a, float4& b, uint4 u, float s) {
    float2 f;
    f = __half22float2(*(const __half2*)&u.x); a.x += s * f.x; a.y += s * f.y;
    f = __half22float2(*(const __half2*)&u.y); a.z += s * f.x; a.w += s * f.y;
    f = __half22float2(*(const __half2*)&u.z); b.x += s * f.x; b.y += s * f.y;
    f = __half22float2(*(const __half2*)&u.w); b.z += s * f.x; b.w += s * f.y;
}

__global__ __launch_bounds__(128) void k_spmm(const float* __restrict__ bias,
                                              float* __restrict__ out) {
    __shared__ unsigned int smask[MW];
    __shared__ unsigned short list[LIST_CAP];
    __shared__ int wsum[4];
    __shared__ __align__(16) float part[64 * 8];

    int row  = blockIdx.x;
    int tid  = threadIdx.x;
    int lane = tid & 31;
    int wrp  = tid >> 5;

    smask[tid]       = g_mask[row * MW + tid];
    smask[tid + 128] = g_mask[row * MW + tid + 128];
    __syncthreads();

    unsigned int w0 = smask[2 * tid], w1 = smask[2 * tid + 1];
    int c = __popc(w0) + __popc(w1);
    int p = c;
    #pragma unroll
    for (int o = 1; o < 32; o <<= 1) {
        int t = __shfl_up_sync(0xffffffffu, p, o);
        if (lane >= o) p += t;
    }
    if (lane == 31) wsum[wrp] = p;
    __syncthreads();
    int wbase = 0;
    #pragma unroll
    for (int w = 0; w < 4; w++) wbase += (w < wrp) ? wsum[w] : 0;
    int total = wsum[0] + wsum[1] + wsum[2] + wsum[3];

    float dinv_i = rsqrtf((float)(total + 1));

    bool uselist = (total <= LIST_CAP);
    if (uselist) {
        int off = wbase + p - c;
        unsigned int bits = w0;
        int base = (2 * tid) << 5;
        while (bits) { int b = __ffs(bits) - 1; bits &= bits - 1; list[off++] = (unsigned short)(base + b); }
        bits = w1; base = (2 * tid + 1) << 5;
        while (bits) { int b = __ffs(bits) - 1; bits &= bits - 1; list[off++] = (unsigned short)(base + b); }
    }
    __syncthreads();

    int tid2 = tid & 63;
    int half = tid >> 6;

    const uint4* H4 = (const uint4*)g_h;

    float4 a0 = make_float4(0,0,0,0), b0 = make_float4(0,0,0,0);
    float4 a1 = make_float4(0,0,0,0), b1 = make_float4(0,0,0,0);
    float4 a2 = make_float4(0,0,0,0), b2 = make_float4(0,0,0,0);
    float4 a3 = make_float4(0,0,0,0), b3 = make_float4(0,0,0,0);

    if (half == 0) fma_h8(a0, b0, H4[row * 64 + tid2], dinv_i);   // identity

    if (uselist) {
        int mid = total >> 1;
        int lo = half ? mid : 0;
        int hi = half ? total : mid;
        int i = lo;
        for (; i + 4 <= hi; i += 4) {
            int j0 = list[i], j1 = list[i + 1], j2 = list[i + 2], j3 = list[i + 3];
            float s0v = g_dinv[j0], s1v = g_dinv[j1], s2v = g_dinv[j2], s3v = g_dinv[j3];
            uint4 u0 = H4[j0 * 64 + tid2];
            uint4 u1 = H4[j1 * 64 + tid2];
            uint4 u2 = H4[j2 * 64 + tid2];
            uint4 u3 = H4[j3 * 64 + tid2];
            fma_h8(a0, b0, u0, s0v);
            fma_h8(a1, b1, u1, s1v);
            fma_h8(a2, b2, u2, s2v);
            fma_h8(a3, b3, u3, s3v);
        }
        for (; i < hi; i++) {
            int j = list[i];
            fma_h8(a0, b0, H4[j * 64 + tid2], g_dinv[j]);
        }
    } else {
        for (int w = half * 128; w < half * 128 + 128; w++) {
            unsigned int bits = smask[w];
            while (bits) {
                int b = __ffs(bits) - 1;
                bits &= bits - 1;
                int j = (w << 5) + b;
                fma_h8(a0, b0, H4[j * 64 + tid2], g_dinv[j]);
            }
        }
    }

    a0.x += a1.x + a2.x + a3.x;  a0.y += a1.y + a2.y + a3.y;
    a0.z += a1.z + a2.z + a3.z;  a0.w += a1.w + a2.w + a3.w;
    b0.x += b1.x + b2.x + b3.x;  b0.y += b1.y + b2.y + b3.y;
    b0.z += b1.z + b2.z + b3.z;  b0.w += b1.w + b2.w + b3.w;

    if (half == 1) {
        ((float4*)part)[tid2 * 2]     = a0;
        ((float4*)part)[tid2 * 2 + 1] = b0;
    }
    __syncthreads();
    if (half == 0) {
        float4 pa = ((float4*)part)[tid2 * 2];
        float4 pb = ((float4*)part)[tid2 * 2 + 1];
        a0.x += pa.x; a0.y += pa.y; a0.z += pa.z; a0.w += pa.w;
        b0.x += pb.x; b0.y += pb.y; b0.z += pb.z; b0.w += pb.w;

        float4 bia = ((const float4*)bias)[tid2 * 2];
        float4 bib = ((const float4*)bias)[tid2 * 2 + 1];
        float4 o0, o1;
        o0.x = dinv_i * a0.x + bia.x; o0.y = dinv_i * a0.y + bia.y;
        o0.z = dinv_i * a0.z + bia.z; o0.w = dinv_i * a0.w + bia.w;
        o1.x = dinv_i * b0.x + bib.x; o1.y = dinv_i * b0.y + bib.y;
        o1.z = dinv_i * b0.z + bib.z; o1.w = dinv_i * b0.w + bib.w;
        ((float4*)out)[row * (D / 4) + tid2 * 2]     = o0;
        ((float4*)out)[row * (D / 4) + tid2 * 2 + 1] = o1;
    }
}

// ---------------------------------------------------------------------------
// launch:
//   stream0: detect -> zero -> scatter -> degree -> (wait evJoin) -> spmm
//   s2:      (wait evFork) cvt_xw -> gemm -> record evJoin
// ---------------------------------------------------------------------------
extern "C" void kernel_launch(void* const* d_in, const int* in_sizes, int n_in,
                              void* d_out, int out_size) {
    const float* x    = (const float*)d_in[0];
    const void*  ei   = d_in[1];
    const float* w    = (const float*)d_in[2];
    const float* bias = (const float*)d_in[3];
    float*       out  = (float*)d_out;

    static cudaStream_t s2 = nullptr;
    static cudaEvent_t evFork = nullptr, evJoin = nullptr;
    if (s2 == nullptr) {
        cudaStreamCreateWithFlags(&s2, cudaStreamNonBlocking);
        cudaEventCreateWithFlags(&evFork, cudaEventDisableTiming);
        cudaEventCreateWithFlags(&evJoin, cudaEventDisableTiming);
        cudaFuncSetAttribute(k_gemm_mma, cudaFuncAttributeMaxDynamicSharedMemorySize,
                             SMEM_GEMM);
    }

    __half *xh, *wh;
    cudaGetSymbolAddress((void**)&xh, g_xh);
    cudaGetSymbolAddress((void**)&wh, g_wh);

    // fork: side chain (cvt -> GEMM) is independent of the graph setup
    cudaEventRecord(evFork, 0);
    cudaStreamWaitEvent(s2, evFork, 0);

    k_cvt_xw<<<XBLOCKS + WBLOCKS, 256, 0, s2>>>((const float4*)x, (uint4*)xh,
                                                (const float4*)w, (uint4*)wh);
    dim3 gemmGrid(D / GBN, N_NODES / GBM);   // (4, 64) = 256 CTAs
    k_gemm_mma<<<gemmGrid, 128, SMEM_GEMM, s2>>>();
    cudaEventRecord(evJoin, s2);

    // main chain
    k_detect<<<1, 128>>>((const int*)ei);
    k_zero_mask<<<512, 256>>>();
    k_scatter<<<(N_EDGES / 2 + 255) / 256, 256>>>(ei);
    k_degree<<<N_NODES / 8, 256>>>();

    // join, then SpMM
    cudaStreamWaitEvent(0, evJoin, 0);
    k_spmm<<<N_NODES, 128>>>(bias, out);
}

// round 17
// speedup vs baseline: 1.0174x; 1.0174x over previous
#include <cuda_runtime.h>
#include <cuda_fp16.h>
#include <cstdint>

#define N_NODES 8192
#define N_EDGES 262144
#define D 512
#define MW 256   // 8192 bits / 32 = 256 mask words per row

// Scratch (device globals; no allocations allowed)
__device__ unsigned int g_mask[N_NODES * MW];           // 8 MB adjacency bitmask
__device__ float        g_dinv[N_NODES];                // D^{-1/2}
__device__ __align__(16) __half g_h[N_NODES * D];       // H = X@W (UNscaled), fp16
__device__ int          g_is64;                         // edge_index dtype flag
__device__ __align__(16) __half g_wh[D * D];            // fp16 W

// ---------------------------------------------------------------------------
// 0) detect edge_index dtype (int64 vs int32): sample 512 odd int32 words.
// ---------------------------------------------------------------------------
__global__ void k_detect(const int* __restrict__ ei32) {
    int t = threadIdx.x;                   // 0..127
    const int4* p = (const int4*)ei32;
    int4 a = p[2 * t];
    int4 b = p[2 * t + 1];
    int nz = a.y | a.w | b.y | b.w;
    int any = __syncthreads_or(nz != 0);
    if (t == 0) g_is64 = any ? 0 : 1;
}

// ---------------------------------------------------------------------------
// 1) zero bitmask
// ---------------------------------------------------------------------------
__global__ void k_zero_mask() {
    int i = blockIdx.x * blockDim.x + threadIdx.x;   // 512 blocks x 256 thr
    uint4* p = (uint4*)g_mask;
    uint4 z = make_uint4(0, 0, 0, 0);
    #pragma unroll
    for (int k = 0; k < 4; k++)
        p[i + k * 131072] = z;
}

// ---------------------------------------------------------------------------
// 2) symmetric edge scatter, 2 edges per thread
// ---------------------------------------------------------------------------
__global__ void k_scatter(const void* __restrict__ ei_raw) {
    int e2 = blockIdx.x * blockDim.x + threadIdx.x;
    if (e2 >= N_EDGES / 2) return;
    int u0, u1, v0, v1;
    if (g_is64) {
        const longlong2* pe = (const longlong2*)ei_raw;
        longlong2 uu = pe[e2];
        longlong2 vv = pe[N_EDGES / 2 + e2];
        u0 = (int)uu.x; u1 = (int)uu.y;
        v0 = (int)vv.x; v1 = (int)vv.y;
    } else {
        const int2* pe = (const int2*)ei_raw;
        int2 uu = pe[e2];
        int2 vv = pe[N_EDGES / 2 + e2];
        u0 = uu.x; u1 = uu.y;
        v0 = vv.x; v1 = vv.y;
    }
    u0 &= (N_NODES - 1); u1 &= (N_NODES - 1);
    v0 &= (N_NODES - 1); v1 &= (N_NODES - 1);
    atomicOr(&g_mask[u0 * MW + (v0 >> 5)], 1u << (v0 & 31));
    atomicOr(&g_mask[v0 * MW + (u0 >> 5)], 1u << (u0 & 31));
    atomicOr(&g_mask[u1 * MW + (v1 >> 5)], 1u << (v1 & 31));
    atomicOr(&g_mask[v1 * MW + (u1 >> 5)], 1u << (u1 & 31));
}

// ---------------------------------------------------------------------------
// 3) degree + dinv
// ---------------------------------------------------------------------------
__global__ void k_degree() {
    int row  = blockIdx.x * (blockDim.x >> 5) + (threadIdx.x >> 5);
    int lane = threadIdx.x & 31;
    if (row >= N_NODES) return;
    const uint4* m = (const uint4*)&g_mask[row * MW];
    int cnt = 0;
    #pragma unroll
    for (int w = 0; w < 2; w++) {
        uint4 q = m[lane + w * 32];
        cnt += __popc(q.x) + __popc(q.y) + __popc(q.z) + __popc(q.w);
    }
    #pragma unroll
    for (int o = 16; o; o >>= 1) cnt += __shfl_xor_sync(0xffffffffu, cnt, o);
    if (lane == 0) g_dinv[row] = rsqrtf((float)(cnt + 1));
}

// ---------------------------------------------------------------------------
// 3b) W only: fp32 -> fp16, 16 floats per thread (64 blocks x 256 thr)
// ---------------------------------------------------------------------------
__global__ void k_cvt_w(const float4* __restrict__ w, uint4* __restrict__ wh) {
    int i = blockIdx.x * blockDim.x + threadIdx.x;   // 0..16383
    float4 a0 = w[4 * i];
    float4 a1 = w[4 * i + 1];
    float4 a2 = w[4 * i + 2];
    float4 a3 = w[4 * i + 3];
    uint4 o0, o1;
    __half2 h;
    h = __floats2half2_rn(a0.x, a0.y); o0.x = *(uint32_t*)&h;
    h = __floats2half2_rn(a0.z, a0.w); o0.y = *(uint32_t*)&h;
    h = __floats2half2_rn(a1.x, a1.y); o0.z = *(uint32_t*)&h;
    h = __floats2half2_rn(a1.z, a1.w); o0.w = *(uint32_t*)&h;
    h = __floats2half2_rn(a2.x, a2.y); o1.x = *(uint32_t*)&h;
    h = __floats2half2_rn(a2.z, a2.w); o1.y = *(uint32_t*)&h;
    h = __floats2half2_rn(a3.x, a3.y); o1.z = *(uint32_t*)&h;
    h = __floats2half2_rn(a3.z, a3.w); o1.w = *(uint32_t*)&h;
    wh[2 * i]     = o0;
    wh[2 * i + 1] = o1;
}

// ---------------------------------------------------------------------------
// 4) Tensor-core GEMM (mma.sync fp16, fp32 acc).
//    NEW: A (=X) is read fp32 DIRECTLY from the input via register-staged
//    LDG.128, converted in-register, stored to a double-buffered fp16 A smem
//    (no separate X conversion kernel). B (=W fp16) keeps the 4-stage
//    cp.async pipeline. 128x128 CTA tile, 4 warps, 64x64 warp tile.
// ---------------------------------------------------------------------------
#define GBM 128
#define GBN 128
#define GBK 32
#define ASTRIDE 40    // halves: 32 + 8 pad (80 B/row)
#define BSTRIDE 144   // halves: 128 + 16 pad (288 B/row)
#define NSTAGE 4
#define A_BYTES (GBM * ASTRIDE * 2)          // 10240
#define B_BYTES (GBK * BSTRIDE * 2)          // 9216
#define BOFF 0
#define AOFF (NSTAGE * B_BYTES)              // 36864
#define SMEM_GEMM (AOFF + 2 * A_BYTES)       // 57344
#define KTILES (D / GBK)                     // 16

__device__ __forceinline__ uint32_t smem_u32(const void* p) {
    uint32_t a;
    asm("{ .reg .u64 t; cvta.to.shared.u64 t, %1; cvt.u32.u64 %0, t; }" : "=r"(a) : "l"(p));
    return a;
}
__device__ __forceinline__ void cp16(uint32_t dst, const void* src) {
    asm volatile("cp.async.cg.shared.global [%0], [%1], 16;" :: "r"(dst), "l"(src) : "memory");
}
__device__ __forceinline__ void ldsm_x4(uint32_t* r, const void* p) {
    uint32_t a = (uint32_t)__cvta_generic_to_shared(p);
    asm volatile("ldmatrix.sync.aligned.m8n8.x4.shared.b16 {%0,%1,%2,%3}, [%4];"
                 : "=r"(r[0]), "=r"(r[1]), "=r"(r[2]), "=r"(r[3]) : "r"(a));
}
__device__ __forceinline__ void ldsm_x4t(uint32_t* r, const void* p) {
    uint32_t a = (uint32_t)__cvta_generic_to_shared(p);
    asm volatile("ldmatrix.sync.aligned.m8n8.x4.trans.shared.b16 {%0,%1,%2,%3}, [%4];"
                 : "=r"(r[0]), "=r"(r[1]), "=r"(r[2]), "=r"(r[3]) : "r"(a));
}
__device__ __forceinline__ void mma16816(float* c, const uint32_t* a, const uint32_t* b) {
    asm volatile("mma.sync.aligned.m16n8k16.row.col.f32.f16.f16.f32 "
                 "{%0,%1,%2,%3}, {%4,%5,%6,%7}, {%8,%9}, {%0,%1,%2,%3};"
                 : "+f"(c[0]), "+f"(c[1]), "+f"(c[2]), "+f"(c[3])
                 : "r"(a[0]), "r"(a[1]), "r"(a[2]), "r"(a[3]), "r"(b[0]), "r"(b[1]));
}

__global__ __launch_bounds__(128) void k_gemm_mma(const float4* __restrict__ X4) {
    extern __shared__ char dsm[];
    uint32_t sb = smem_u32(dsm);

    int tid  = threadIdx.x;            // 0..127
    int lane = tid & 31;
    int wid  = tid >> 5;               // 0..3
    int wm   = wid & 1;                // rows wm*64
    int wn   = wid >> 1;               // cols wn*64
    int rowBase = blockIdx.y * GBM;
    int colBase = blockIdx.x * GBN;

    float acc[4][8][4];
    #pragma unroll
    for (int mi = 0; mi < 4; mi++)
        #pragma unroll
        for (int ni = 0; ni < 8; ni++)
            #pragma unroll
            for (int q = 0; q < 4; q++) acc[mi][ni][q] = 0.0f;

    // A: register staging of fp32 X (8 float4 per thread per tile)
    float4 rA[8];
    auto ldgA = [&](int t) {
        #pragma unroll
        for (int k = 0; k < 8; k++) {
            int j = tid + k * 128;                 // chunk 0..1023
            int r = j >> 3, c4 = j & 7;            // row, float4-col
            rA[k] = X4[(rowBase + r) * (D / 4) + t * 8 + c4];
        }
    };
    auto stsA = [&](int t) {
        char* abuf = dsm + AOFF + (t & 1) * A_BYTES;
        #pragma unroll
        for (int k = 0; k < 8; k++) {
            int j = tid + k * 128;
            int r = j >> 3, c4 = j & 7;
            __half2 h0 = __floats2half2_rn(rA[k].x, rA[k].y);
            __half2 h1 = __floats2half2_rn(rA[k].z, rA[k].w);
            uint2 u;
            u.x = *(uint32_t*)&h0;
            u.y = *(uint32_t*)&h1;
            *(uint2*)(abuf + r * (ASTRIDE * 2) + c4 * 8) = u;
        }
    };

    // B: cp.async pipeline (4 x 16B per thread per tile)
    auto issueB = [&](int t) {
        uint32_t base = sb + BOFF + (t % NSTAGE) * B_BYTES;
        #pragma unroll
        for (int k = 0; k < 4; k++) {
            int i = tid + k * 128;
            int r = i >> 4, cc = i & 15;
            cp16(base + r * 288 + cc * 16,
                 &g_wh[(t * GBK + r) * D + colBase + cc * 8]);
        }
        asm volatile("cp.async.commit_group;" ::: "memory");
    };

    ldgA(0);
    #pragma unroll
    for (int t = 0; t < NSTAGE - 1; t++) issueB(t);

    for (int kt = 0; kt < KTILES; kt++) {
        __syncthreads();                       // prior tile's compute done
        stsA(kt);                              // A tile kt -> buf kt&1
        if (kt + 1 < KTILES) ldgA(kt + 1);     // prefetch next A (hidden)
        if (kt + NSTAGE - 1 < KTILES) issueB(kt + NSTAGE - 1);
        else asm volatile("cp.async.commit_group;" ::: "memory");
        asm volatile("cp.async.wait_group %0;" :: "n"(NSTAGE - 1) : "memory");
        __syncthreads();                       // A buf + B stage visible

        const __half* Ah = (const __half*)(dsm + AOFF + (kt & 1) * A_BYTES);
        const __half* Bh = (const __half*)(dsm + BOFF + (kt % NSTAGE) * B_BYTES);

        #pragma unroll
        for (int kk = 0; kk < GBK; kk += 16) {
            uint32_t af[4][4];
            #pragma unroll
            for (int mi = 0; mi < 4; mi++) {
                int r = wm * 64 + mi * 16 + (lane & 15);
                int c = kk + ((lane >> 4) << 3);
                ldsm_x4(af[mi], &Ah[r * ASTRIDE + c]);
            }
            uint32_t bf[8][2];
            #pragma unroll
            for (int np = 0; np < 4; np++) {
                int r = kk + (lane & 15);
                int c = wn * 64 + np * 16 + ((lane >> 4) << 3);
                uint32_t t4[4];
                ldsm_x4t(t4, &Bh[r * BSTRIDE + c]);
                bf[2 * np][0] = t4[0]; bf[2 * np][1] = t4[1];
                bf[2 * np + 1][0] = t4[2]; bf[2 * np + 1][1] = t4[3];
            }
            #pragma unroll
            for (int mi = 0; mi < 4; mi++)
                #pragma unroll
                for (int ni = 0; ni < 8; ni++)
                    mma16816(acc[mi][ni], af[mi], bf[ni]);
        }
    }

    // epilogue: write fp16 H (no scaling)
    int g  = lane >> 2;
    int tg = lane & 3;
    #pragma unroll
    for (int mi = 0; mi < 4; mi++) {
        int row0 = rowBase + wm * 64 + mi * 16 + g;
        int row1 = row0 + 8;
        #pragma unroll
        for (int ni = 0; ni < 8; ni++) {
            int col = colBase + wn * 64 + ni * 8 + tg * 2;
            __half2 v0 = __floats2half2_rn(acc[mi][ni][0], acc[mi][ni][1]);
            __half2 v1 = __floats2half2_rn(acc[mi][ni][2], acc[mi][ni][3]);
            *(__half2*)&g_h[row0 * D + col] = v0;
            *(__half2*)&g_h[row1 * D + col] = v1;
        }
    }
}

// ---------------------------------------------------------------------------
// 5) SpMM gather (fp16 payload, 16B loads, per-neighbor dinv scaling)
// ---------------------------------------------------------------------------
#define LIST_CAP 4096

__device__ __forceinline__ void fma_h8(float4& a, float4& b, uint4 u, float s) {
    float2 f;
    f = __half22float2(*(const __half2*)&u.x); a.x += s * f.x; a.y += s * f.y;
    f = __half22float2(*(const __half2*)&u.y); a.z += s * f.x; a.w += s * f.y;
    f = __half22float2(*(const __half2*)&u.z); b.x += s * f.x; b.y += s * f.y;
    f = __half22float2(*(const __half2*)&u.w); b.z += s * f.x; b.w += s * f.y;
}

__global__ __launch_bounds__(128) void k_spmm(const float* __restrict__ bias,
                                              float* __restrict__ out) {
    __shared__ unsigned int smask[MW];
    __shared__ unsigned short list[LIST_CAP];
    __shared__ int wsum[4];
    __shared__ __align__(16) float part[64 * 8];

    int row  = blockIdx.x;
    int tid  = threadIdx.x;
    int lane = tid & 31;
    int wrp  = tid >> 5;

    smask[tid]       = g_mask[row * MW + tid];
    smask[tid + 128] = g_mask[row * MW + tid + 128];
    __syncthreads();

    unsigned int w0 = smask[2 * tid], w1 = smask[2 * tid + 1];
    int c = __popc(w0) + __popc(w1);
    int p = c;
    #pragma unroll
    for (int o = 1; o < 32; o <<= 1) {
        int t = __shfl_up_sync(0xffffffffu, p, o);
        if (lane >= o) p += t;
    }
    if (lane == 31) wsum[wrp] = p;
    __syncthreads();
    int wbase = 0;
    #pragma unroll
    for (int w = 0; w < 4; w++) wbase += (w < wrp) ? wsum[w] : 0;
    int total = wsum[0] + wsum[1] + wsum[2] + wsum[3];

    float dinv_i = rsqrtf((float)(total + 1));

    bool uselist = (total <= LIST_CAP);
    if (uselist) {
        int off = wbase + p - c;
        unsigned int bits = w0;
        int base = (2 * tid) << 5;
        while (bits) { int b = __ffs(bits) - 1; bits &= bits - 1; list[off++] = (unsigned short)(base + b); }
        bits = w1; base = (2 * tid + 1) << 5;
        while (bits) { int b = __ffs(bits) - 1; bits &= bits - 1; list[off++] = (unsigned short)(base + b); }
    }
    __syncthreads();

    int tid2 = tid & 63;
    int half = tid >> 6;

    const uint4* H4 = (const uint4*)g_h;

    float4 a0 = make_float4(0,0,0,0), b0 = make_float4(0,0,0,0);
    float4 a1 = make_float4(0,0,0,0), b1 = make_float4(0,0,0,0);
    float4 a2 = make_float4(0,0,0,0), b2 = make_float4(0,0,0,0);
    float4 a3 = make_float4(0,0,0,0), b3 = make_float4(0,0,0,0);

    if (half == 0) fma_h8(a0, b0, H4[row * 64 + tid2], dinv_i);   // identity

    if (uselist) {
        int mid = total >> 1;
        int lo = half ? mid : 0;
        int hi = half ? total : mid;
        int i = lo;
        for (; i + 4 <= hi; i += 4) {
            int j0 = list[i], j1 = list[i + 1], j2 = list[i + 2], j3 = list[i + 3];
            float s0v = g_dinv[j0], s1v = g_dinv[j1], s2v = g_dinv[j2], s3v = g_dinv[j3];
            uint4 u0 = H4[j0 * 64 + tid2];
            uint4 u1 = H4[j1 * 64 + tid2];
            uint4 u2 = H4[j2 * 64 + tid2];
            uint4 u3 = H4[j3 * 64 + tid2];
            fma_h8(a0, b0, u0, s0v);
            fma_h8(a1, b1, u1, s1v);
            fma_h8(a2, b2, u2, s2v);
            fma_h8(a3, b3, u3, s3v);
        }
        for (; i < hi; i++) {
            int j = list[i];
            fma_h8(a0, b0, H4[j * 64 + tid2], g_dinv[j]);
        }
    } else {
        for (int w = half * 128; w < half * 128 + 128; w++) {
            unsigned int bits = smask[w];
            while (bits) {
                int b = __ffs(bits) - 1;
                bits &= bits - 1;
                int j = (w << 5) + b;
                fma_h8(a0, b0, H4[j * 64 + tid2], g_dinv[j]);
            }
        }
    }

    a0.x += a1.x + a2.x + a3.x;  a0.y += a1.y + a2.y + a3.y;
    a0.z += a1.z + a2.z + a3.z;  a0.w += a1.w + a2.w + a3.w;
    b0.x += b1.x + b2.x + b3.x;  b0.y += b1.y + b2.y + b3.y;
    b0.z += b1.z + b2.z + b3.z;  b0.w += b1.w + b2.w + b3.w;

    if (half == 1) {
        ((float4*)part)[tid2 * 2]     = a0;
        ((float4*)part)[tid2 * 2 + 1] = b0;
    }
    __syncthreads();
    if (half == 0) {
        float4 pa = ((float4*)part)[tid2 * 2];
        float4 pb = ((float4*)part)[tid2 * 2 + 1];
        a0.x += pa.x; a0.y += pa.y; a0.z += pa.z; a0.w += pa.w;
        b0.x += pb.x; b0.y += pb.y; b0.z += pb.z; b0.w += pb.w;

        float4 bia = ((const float4*)bias)[tid2 * 2];
        float4 bib = ((const float4*)bias)[tid2 * 2 + 1];
        float4 o0, o1;
        o0.x = dinv_i * a0.x + bia.x; o0.y = dinv_i * a0.y + bia.y;
        o0.z = dinv_i * a0.z + bia.z; o0.w = dinv_i * a0.w + bia.w;
        o1.x = dinv_i * b0.x + bib.x; o1.y = dinv_i * b0.y + bib.y;
        o1.z = dinv_i * b0.z + bib.z; o1.w = dinv_i * b0.w + bib.w;
        ((float4*)out)[row * (D / 4) + tid2 * 2]     = o0;
        ((float4*)out)[row * (D / 4) + tid2 * 2 + 1] = o1;
    }
}

// ---------------------------------------------------------------------------
// launch:
//   stream0: detect -> zero -> scatter -> degree -> (wait evJoin) -> spmm
//   s2:      (wait evFork) cvtW (tiny) -> gemm (inline X convert) -> evJoin
// ---------------------------------------------------------------------------
extern "C" void kernel_launch(void* const* d_in, const int* in_sizes, int n_in,
                              void* d_out, int out_size) {
    const float* x    = (const float*)d_in[0];
    const void*  ei   = d_in[1];
    const float* w    = (const float*)d_in[2];
    const float* bias = (const float*)d_in[3];
    float*       out  = (float*)d_out;

    static cudaStream_t s2 = nullptr;
    static cudaEvent_t evFork = nullptr, evJoin = nullptr;
    if (s2 == nullptr) {
        cudaStreamCreateWithFlags(&s2, cudaStreamNonBlocking);
        cudaEventCreateWithFlags(&evFork, cudaEventDisableTiming);
        cudaEventCreateWithFlags(&evJoin, cudaEventDisableTiming);
        cudaFuncSetAttribute(k_gemm_mma, cudaFuncAttributeMaxDynamicSharedMemorySize,
                             SMEM_GEMM);
    }

    __half* wh;
    cudaGetSymbolAddress((void**)&wh, g_wh);

    // fork: side chain (cvtW -> GEMM) is independent of the graph setup
    cudaEventRecord(evFork, 0);
    cudaStreamWaitEvent(s2, evFork, 0);

    k_cvt_w<<<64, 256, 0, s2>>>((const float4*)w, (uint4*)wh);
    dim3 gemmGrid(D / GBN, N_NODES / GBM);   // (4, 64) = 256 CTAs
    k_gemm_mma<<<gemmGrid, 128, SMEM_GEMM, s2>>>((const float4*)x);
    cudaEventRecord(evJoin, s2);

    // main chain
    k_detect<<<1, 128>>>((const int*)ei);
    k_zero_mask<<<512, 256>>>();
    k_scatter<<<(N_EDGES / 2 + 255) / 256, 256>>>(ei);
    k_degree<<<N_NODES / 8, 256>>>();

    // join, then SpMM
    cudaStreamWaitEvent(0, evJoin, 0);
    k_spmm<<<N_NODES, 128>>>(bias, out);
}